// round 4
// baseline (speedup 1.0000x reference)
#include <cuda_runtime.h>
#include <cuda_bf16.h>

// loss[s] = -(1/496)*[ sum_i x_i*(31-i) - sum_{i<j} ln(e_i+e_j) + 0.0005*sum_i x_i^2*(31-2i) ]
// via log_sigmoid(x_i - x_j) == x_i - ln(e^{x_i} + e^{x_j}).
//
// sum_{pairs} ln(t) = ln(prod t): each lane multiplies its 16 pair terms into
// TWO 8-term fp32 products (no renorm needed: 8 terms stay within 2^+-72),
// one lg2 per lane at the end. 4 segments per warp (2 packed f32x2 chains)
// for latency hiding.

static constexpr float INV_PAIRS = 1.0f / 496.0f;
static constexpr float LN2  = 0.69314718055994530942f;
static constexpr float L2E  = 1.44269504088896340736f;
static constexpr int   WPB  = 8;   // warps per block

typedef unsigned long long u64;
typedef unsigned int u32;

__device__ __forceinline__ u64 pk(float lo, float hi) {
    u64 r; asm("mov.b64 %0,{%1,%2};" : "=l"(r) : "f"(lo), "f"(hi)); return r;
}
__device__ __forceinline__ void upk(u64 v, float& lo, float& hi) {
    asm("mov.b64 {%0,%1},%2;" : "=f"(lo), "=f"(hi) : "l"(v));
}
__device__ __forceinline__ u64 add2(u64 a, u64 b) {
    u64 r; asm("add.rn.f32x2 %0,%1,%2;" : "=l"(r) : "l"(a), "l"(b)); return r;
}
__device__ __forceinline__ u64 mul2(u64 a, u64 b) {
    u64 r; asm("mul.rn.f32x2 %0,%1,%2;" : "=l"(r) : "l"(a), "l"(b)); return r;
}
__device__ __forceinline__ u64 fma2(u64 a, u64 b, u64 c) {
    u64 r; asm("fma.rn.f32x2 %0,%1,%2,%3;" : "=l"(r) : "l"(a), "l"(b), "l"(c)); return r;
}
__device__ __forceinline__ float ex2(float x) {
    float r; asm("ex2.approx.f32 %0,%1;" : "=f"(r) : "f"(x)); return r;
}
__device__ __forceinline__ float lg2(float x) {
    float r; asm("lg2.approx.f32 %0,%1;" : "=f"(r) : "f"(x)); return r;
}
// Split packed value into packed mantissas in [1,2) and raw exponents.
__device__ __forceinline__ void manexp(u64 p, u64& m, int& eL, int& eH) {
    float a, b; upk(p, a, b);
    u32 ba = __float_as_uint(a), bb = __float_as_uint(b);
    eL = (int)(ba >> 23);
    eH = (int)(bb >> 23);
    m = pk(__uint_as_float((ba & 0x007FFFFFu) | 0x3F800000u),
           __uint_as_float((bb & 0x007FFFFFu) | 0x3F800000u));
}

__global__ __launch_bounds__(WPB * 32)
void rmloss_kernel(const float* __restrict__ logits,
                   float4* __restrict__ out,
                   int n_seg)
{
    __shared__ u64 sh01[WPB][64];
    __shared__ u64 sh23[WPB][64];

    const int w    = threadIdx.x >> 5;
    const int lane = threadIdx.x & 31;
    const int gw   = blockIdx.x * WPB + w;          // warp index
    const int s0   = gw * 4;                        // 4 segments per warp
    if (s0 >= n_seg) return;

    const float* base = logits + s0 * 32 + lane;
    const u64 x01 = pk(base[0],  base[32]);
    const u64 x23 = pk(base[64], base[96]);

    // e = exp(x) = exp2(x * log2e)
    const u64 ks = pk(L2E, L2E);
    u64 t01 = mul2(x01, ks), t23 = mul2(x23, ks);
    float a, b, c, d;
    upk(t01, a, b); upk(t23, c, d);
    const u64 e01 = pk(ex2(a), ex2(b));
    const u64 e23 = pk(ex2(c), ex2(d));

    // Duplicated rings -> pair reads are LDS.64 [base + imm].
    sh01[w][lane] = e01;  sh01[w][lane + 32] = e01;
    sh23[w][lane] = e23;  sh23[w][lane + 32] = e23;
    __syncwarp();

    // Products of pair terms (e_l + e_{l+o}). Offsets 1..15: each unordered
    // pair once. Offset 16: only lanes 0..15 (mask others to 1.0).
    // Two 8-term accumulators per chain: no renorm needed (2^+-72 range).
    u64 pa01 = add2(e01, sh01[w][lane + 1]);
    u64 pa23 = add2(e23, sh23[w][lane + 1]);
    #pragma unroll
    for (int o = 2; o <= 8; ++o) {
        pa01 = mul2(pa01, add2(e01, sh01[w][lane + o]));
        pa23 = mul2(pa23, add2(e23, sh23[w][lane + o]));
    }
    u64 pb01 = add2(e01, sh01[w][lane + 9]);
    u64 pb23 = add2(e23, sh23[w][lane + 9]);
    #pragma unroll
    for (int o = 10; o <= 15; ++o) {
        pb01 = mul2(pb01, add2(e01, sh01[w][lane + o]));
        pb23 = mul2(pb23, add2(e23, sh23[w][lane + o]));
    }
    {   // offset 16, masked on upper half-warp
        u64 one = pk(1.0f, 1.0f);
        u64 t0 = (lane < 16) ? add2(e01, sh01[w][lane + 16]) : one;
        u64 t1 = (lane < 16) ? add2(e23, sh23[w][lane + 16]) : one;
        pb01 = mul2(pb01, t0);
        pb23 = mul2(pb23, t1);
    }

    // log2(pa*pb) = (Ea + Eb - 254) + lg2(ma*mb), ma*mb in [1,4).
    u64 ma01, mb01, ma23, mb23;
    int eaL, eaH, ebL, ebH, ecL, ecH, edL, edH;
    manexp(pa01, ma01, eaL, eaH);
    manexp(pb01, mb01, ebL, ebH);
    manexp(pa23, ma23, ecL, ecH);
    manexp(pb23, mb23, edL, edH);
    u64 mm01 = mul2(ma01, mb01);
    u64 mm23 = mul2(ma23, mb23);
    float m0, m1, m2, m3;
    upk(mm01, m0, m1); upk(mm23, m2, m3);
    const u64 slg01 = pk((float)(eaL + ebL - 254) + lg2(m0),
                         (float)(eaH + ebH - 254) + lg2(m1));
    const u64 slg23 = pk((float)(ecL + edL - 254) + lg2(m2),
                         (float)(ecH + edH - 254) + lg2(m3));

    // Closed-form terms: x*(31-lane) + 0.0005*x^2*(31-2*lane), packed.
    const float clf = (float)(31 - lane);
    const float cqf = 0.0005f * (float)(31 - 2 * lane);
    const u64 cl = pk(clf, clf);
    const u64 cq = pk(cqf, cqf);
    u64 v01 = mul2(x01, cl);
    u64 v23 = mul2(x23, cl);
    v01 = fma2(mul2(x01, x01), cq, v01);
    v23 = fma2(mul2(x23, x23), cq, v23);

    // v -= ln2 * log2(prod)
    const u64 nln2 = pk(-LN2, -LN2);
    v01 = fma2(slg01, nln2, v01);
    v23 = fma2(slg23, nln2, v23);

    // Butterfly reduction: two interleaved independent chains.
    #pragma unroll
    for (int m = 16; m >= 1; m >>= 1) {
        u64 o0 = __shfl_xor_sync(0xFFFFFFFFu, v01, m);
        u64 o1 = __shfl_xor_sync(0xFFFFFFFFu, v23, m);
        v01 = add2(v01, o0);
        v23 = add2(v23, o1);
    }

    if (lane == 0) {
        float vA, vB, vC, vD;
        upk(v01, vA, vB); upk(v23, vC, vD);
        out[gw] = make_float4(-vA * INV_PAIRS, -vB * INV_PAIRS,
                              -vC * INV_PAIRS, -vD * INV_PAIRS);
    }
}

extern "C" void kernel_launch(void* const* d_in, const int* in_sizes, int n_in,
                              void* d_out, int out_size)
{
    const float* logits = (const float*)d_in[0];
    float4* out = (float4*)d_out;
    const int n_seg = out_size;                  // 32768

    const int threads = WPB * 32;                // 8 warps -> 32 segments/block
    const int segs_per_block = WPB * 4;
    const int blocks = (n_seg + segs_per_block - 1) / segs_per_block;
    rmloss_kernel<<<blocks, threads>>>(logits, out, n_seg);
}

// round 5
// speedup vs baseline: 1.0333x; 1.0333x over previous
#include <cuda_runtime.h>
#include <cuda_bf16.h>

// loss[s] = -(1/496)*[ sum_i x_i*(31-i) - sum_{i<j} ln(e_i+e_j) + 0.0005*sum_i x_i^2*(31-2i) ]
// via log_sigmoid(x_i - x_j) == x_i - ln(e^{x_i} + e^{x_j}).
//
// sum_{pairs} ln = ln(prod). Per lane: two renorm-free 8-term fp32 products,
// one lg2 at the end. 4 segments/warp packed as 2 f32x2 chains. Lane-sum via
// block transpose reduction in smem (replaces the shuffle butterfly).
// All scale constants folded into per-lane coefficients.

static constexpr float INV_PAIRS = 1.0f / 496.0f;
static constexpr float LN2  = 0.69314718055994530942f;
static constexpr float L2E  = 1.44269504088896340736f;
static constexpr int   WPB  = 4;                 // warps per block (128 thr)
static constexpr int   SEG_PER_BLOCK = WPB * 4;  // 16

typedef unsigned long long u64;
typedef unsigned int u32;

__device__ __forceinline__ u64 pk(float lo, float hi) {
    u64 r; asm("mov.b64 %0,{%1,%2};" : "=l"(r) : "f"(lo), "f"(hi)); return r;
}
__device__ __forceinline__ void upk(u64 v, float& lo, float& hi) {
    asm("mov.b64 {%0,%1},%2;" : "=f"(lo), "=f"(hi) : "l"(v));
}
__device__ __forceinline__ u64 add2(u64 a, u64 b) {
    u64 r; asm("add.rn.f32x2 %0,%1,%2;" : "=l"(r) : "l"(a), "l"(b)); return r;
}
__device__ __forceinline__ u64 mul2(u64 a, u64 b) {
    u64 r; asm("mul.rn.f32x2 %0,%1,%2;" : "=l"(r) : "l"(a), "l"(b)); return r;
}
__device__ __forceinline__ u64 fma2(u64 a, u64 b, u64 c) {
    u64 r; asm("fma.rn.f32x2 %0,%1,%2,%3;" : "=l"(r) : "l"(a), "l"(b), "l"(c)); return r;
}
__device__ __forceinline__ float ex2(float x) {
    float r; asm("ex2.approx.f32 %0,%1;" : "=f"(r) : "f"(x)); return r;
}
__device__ __forceinline__ float lg2(float x) {
    float r; asm("lg2.approx.f32 %0,%1;" : "=f"(r) : "f"(x)); return r;
}
// Split packed value into packed mantissas in [1,2) and raw exponents.
__device__ __forceinline__ void manexp(u64 p, u64& m, int& eL, int& eH) {
    float a, b; upk(p, a, b);
    u32 ba = __float_as_uint(a), bb = __float_as_uint(b);
    eL = (int)(ba >> 23);
    eH = (int)(bb >> 23);
    m = pk(__uint_as_float((ba & 0x007FFFFFu) | 0x3F800000u),
           __uint_as_float((bb & 0x007FFFFFu) | 0x3F800000u));
}

__global__ __launch_bounds__(WPB * 32)
void rmloss_kernel(const float* __restrict__ logits,
                   float2* __restrict__ out,
                   int n_seg)
{
    __shared__ u64 sh01[WPB][64];
    __shared__ u64 sh23[WPB][64];
    __shared__ u64 red[WPB * 2][33];   // [warp*2+chain][lane], padded

    const int w    = threadIdx.x >> 5;
    const int lane = threadIdx.x & 31;
    const int gw   = blockIdx.x * WPB + w;
    const int s0   = gw * 4;                        // 4 segments per warp
    const bool active = (s0 < n_seg);

    u64 v01 = 0ull, v23 = 0ull;
    if (active) {
        const float* base = logits + s0 * 32 + lane;
        const u64 x01 = pk(base[0],  base[32]);
        const u64 x23 = pk(base[64], base[96]);

        // e = exp(x) = exp2(x * log2e)
        const u64 ks = pk(L2E, L2E);
        u64 t01 = mul2(x01, ks), t23 = mul2(x23, ks);
        float a, b, c, d;
        upk(t01, a, b); upk(t23, c, d);
        const u64 e01 = pk(ex2(a), ex2(b));
        const u64 e23 = pk(ex2(c), ex2(d));

        // Duplicated rings -> pair reads are LDS.64 [base + imm].
        sh01[w][lane] = e01;  sh01[w][lane + 32] = e01;
        sh23[w][lane] = e23;  sh23[w][lane + 32] = e23;
        __syncwarp();

        // Products of pair terms (e_l + e_{l+o}): offsets 1..15 each unordered
        // pair once; offset 16 only lanes 0..15. Two 8-term accumulators
        // (renorm-free: stays within 2^+-72).
        u64 pa01 = add2(e01, sh01[w][lane + 1]);
        u64 pa23 = add2(e23, sh23[w][lane + 1]);
        #pragma unroll
        for (int o = 2; o <= 8; ++o) {
            pa01 = mul2(pa01, add2(e01, sh01[w][lane + o]));
            pa23 = mul2(pa23, add2(e23, sh23[w][lane + o]));
        }
        u64 pb01 = add2(e01, sh01[w][lane + 9]);
        u64 pb23 = add2(e23, sh23[w][lane + 9]);
        #pragma unroll
        for (int o = 10; o <= 15; ++o) {
            pb01 = mul2(pb01, add2(e01, sh01[w][lane + o]));
            pb23 = mul2(pb23, add2(e23, sh23[w][lane + o]));
        }
        if (lane < 16) {   // offset 16 (predicated; inactive lanes multiply by 1)
            pb01 = mul2(pb01, add2(e01, sh01[w][lane + 16]));
            pb23 = mul2(pb23, add2(e23, sh23[w][lane + 16]));
        }

        // log2(pa*pb) = (Ea + Eb - 254) + lg2(ma*mb), ma*mb in [1,4).
        u64 ma01, mb01, ma23, mb23;
        int eaL, eaH, ebL, ebH, ecL, ecH, edL, edH;
        manexp(pa01, ma01, eaL, eaH);
        manexp(pb01, mb01, ebL, ebH);
        manexp(pa23, ma23, ecL, ecH);
        manexp(pb23, mb23, edL, edH);
        u64 mm01 = mul2(ma01, mb01);
        u64 mm23 = mul2(ma23, mb23);
        float m0, m1, m2, m3;
        upk(mm01, m0, m1); upk(mm23, m2, m3);
        const u64 slg01 = pk((float)(eaL + ebL - 254) + lg2(m0),
                             (float)(eaH + ebH - 254) + lg2(m1));
        const u64 slg23 = pk((float)(ecL + edL - 254) + lg2(m2),
                             (float)(ecH + edH - 254) + lg2(m3));

        // Per-lane coefficients with ALL scales folded in:
        //   out = sum_lanes[ x*(-cl/496) + x^2*(-0.0005*cq/496) + slg*(ln2/496) ]
        const float clf = (float)(31 - lane)     * (-INV_PAIRS);
        const float cqf = (float)(31 - 2 * lane) * (-0.0005f * INV_PAIRS);
        const u64 CL  = pk(clf, clf);
        const u64 CQ  = pk(cqf, cqf);
        const u64 CLN = pk(LN2 * INV_PAIRS, LN2 * INV_PAIRS);

        v01 = mul2(x01, CL);
        v23 = mul2(x23, CL);
        v01 = fma2(mul2(x01, x01), CQ, v01);
        v23 = fma2(mul2(x23, x23), CQ, v23);
        v01 = fma2(slg01, CLN, v01);
        v23 = fma2(slg23, CLN, v23);
    }

    // Block transpose reduction: partials to smem, warp 0 sums rows.
    red[w * 2 + 0][lane] = v01;
    red[w * 2 + 1][lane] = v23;
    __syncthreads();

    const int r = threadIdx.x;                       // row = threadIdx for r < 8
    if (r < WPB * 2) {
        // Row r holds 32 lane-partials for segment pair (blockBase + 2r).
        u64 acc0 = red[r][0], acc1 = red[r][1];
        #pragma unroll
        for (int i = 2; i < 32; i += 2) {
            acc0 = add2(acc0, red[r][i]);
            acc1 = add2(acc1, red[r][i + 1]);
        }
        u64 v = add2(acc0, acc1);
        const int segPair = blockIdx.x * (SEG_PER_BLOCK / 2) + r;
        if (segPair * 2 < n_seg) {
            float vA, vB; upk(v, vA, vB);
            out[segPair] = make_float2(vA, vB);
        }
    }
}

extern "C" void kernel_launch(void* const* d_in, const int* in_sizes, int n_in,
                              void* d_out, int out_size)
{
    const float* logits = (const float*)d_in[0];
    float2* out = (float2*)d_out;
    const int n_seg = out_size;                  // 32768

    const int threads = WPB * 32;                // 128
    const int blocks = (n_seg + SEG_PER_BLOCK - 1) / SEG_PER_BLOCK;   // 2048
    rmloss_kernel<<<blocks, threads>>>(logits, out, n_seg);
}